// round 15
// speedup vs baseline: 8.3985x; 1.0258x over previous
#include <cuda_runtime.h>
#include <cuda_fp16.h>
#include <cstdint>
#include <math.h>

#define N_R 50000
#define N_D 10000
#define HH  8
#define DH  32
#define CC  256
#define RNA_IN 256
#define D_FEAT 512
#define E_RD 200000
#define E_DR 200000
#define E_RR 400000
#define E_DD 50000
#define E_TOT (E_RD + E_DR + E_RR + E_DD)
#define CNT_TOT (2 * N_R + 2 * N_D)
#define MP 50048
#define MT (MP + N_D)

// ---------------- static device scratch ------------------------------------
__device__ __half   g_xr_h[(size_t)N_R * RNA_IN];    // fp16 copy of x_rna
__device__ __half   g_xdis_h[(size_t)N_D * D_FEAT];  // fp16 copy of x_disease
__device__ __half   g_xd[N_D * RNA_IN];              // fp16 xd
__device__ __half   g_hr[N_R * CC];
__device__ __half   g_hd[N_D * CC];
__device__ __half   g_bufA[(size_t)MT * CC];
__device__ __half   g_bufB[(size_t)MT * CC];
__device__ float    g_s_rna[4 * N_R * HH];
__device__ float    g_s_dis[4 * N_D * HH];
__device__ int      g_cnt[CNT_TOT];
__device__ int      g_fill[CNT_TOT];
__device__ int      g_rptr[4 * (N_R + 1)];
__device__ int      g_ssort[E_TOT];
__device__ float    g_scores[4];
// fp16 k-linear weights: Wh[((k/32)*N + n)*32 + k%32]
__device__ __half   g_wd_h[D_FEAT * RNA_IN];
__device__ __half   g_wpr_h[RNA_IN * CC];
__device__ __half   g_wpd_h[RNA_IN * CC];
__device__ __half   g_kw_h[CC * CC];
__device__ __half   g_wo_h[CC * CC];

// ================= fp32 -> fp16 conversion ===================================
__global__ void __launch_bounds__(256)
cvt_h_k(const float* __restrict__ x, __half* __restrict__ y, int n)
{
    int i = (blockIdx.x * blockDim.x + threadIdx.x) * 8;
    if (i >= n) return;
    float4 a = *(const float4*)(x + i);
    float4 b = *(const float4*)(x + i + 4);
    __half2 h0 = __floats2half2_rn(a.x, a.y);
    __half2 h1 = __floats2half2_rn(a.z, a.w);
    __half2 h2 = __floats2half2_rn(b.x, b.y);
    __half2 h3 = __floats2half2_rn(b.z, b.w);
    uint4 pk;
    pk.x = *(uint32_t*)&h0; pk.y = *(uint32_t*)&h1;
    pk.z = *(uint32_t*)&h2; pk.w = *(uint32_t*)&h3;
    *(uint4*)(y + i) = pk;
}

// ================= weight prep: all fp16 k-linear ============================
__global__ void __launch_bounds__(256)
prep_w_k(const float* __restrict__ wd,  const float* __restrict__ wpr,
         const float* __restrict__ wpd, const float* __restrict__ kw,
         const float* __restrict__ wo,
         __half* __restrict__ wdh, __half* __restrict__ wprh,
         __half* __restrict__ wpdh,
         __half* __restrict__ kwh, __half* __restrict__ woh)
{
    __shared__ float tile[32][129];
    int b = blockIdx.x;
    const float* src; __half* dst; int N, base;
    if (b < 32)      { src = wd;  dst = wdh;  N = RNA_IN; base = 0;  }
    else if (b < 48) { src = wpr; dst = wprh; N = CC;     base = 32; }
    else if (b < 64) { src = wpd; dst = wpdh; N = CC;     base = 48; }
    else if (b < 80) { src = kw;  dst = kwh;  N = CC;     base = 64; }
    else             { src = wo;  dst = woh;  N = CC;     base = 80; }
    int lb = b - base;
    int ntl = N / 128;
    int kt = lb / ntl, nb = lb % ntl;
    int k0 = kt * 32, n0 = nb * 128;
    int tid = threadIdx.x;
#pragma unroll
    for (int it = 0; it < 16; it++) {
        int idx = it * 256 + tid;
        int k = idx >> 7, n = idx & 127;
        tile[k][n] = src[(size_t)(k0 + k) * N + n0 + n];
    }
    __syncthreads();
#pragma unroll
    for (int it = 0; it < 2; it++) {
        int cidx = it * 256 + tid;
        int n = cidx >> 2, cg = cidx & 3;
        __half hb[8];
#pragma unroll
        for (int j = 0; j < 8; j++) hb[j] = __float2half_rn(tile[cg * 8 + j][n]);
        *(uint4*)&dst[((size_t)kt * N + n0 + n) * 32 + cg * 8] = *(uint4*)hb;
    }
}

// =============================================================================
// fp16 projection GEMM: MODE 0 (fp16 C), MODE 3 (fp16 C + fused head scores)
// A fp16 gmem (cp.async direct), B fp16 k-linear, mma m16n8k16, fp32 acc
// =============================================================================
#define AHH 40
#define SMEM_HP ((4 * 128 * AHH) * 2 + (128 + 512) * 4)

template <int MODE>
__global__ void __launch_bounds__(256, 2)
gemm_hp(const __half* __restrict__ A0, const __half* __restrict__ Bt,
        const float* __restrict__ bias,
        __half* __restrict__ C,
        const float* __restrict__ av0, const float* __restrict__ av1,
        const float* __restrict__ av2, const float* __restrict__ av3,
        float* __restrict__ s0, float* __restrict__ s1,
        float* __restrict__ s2, float* __restrict__ s3,
        int M, int N, int K)
{
    extern __shared__ char smh[];
    __half* Ah = (__half*)smh;
    __half* Bh = Ah + 2 * 128 * AHH;
    float* bias_s = (float*)(Bh + 2 * 128 * AHH);
    float* avs    = bias_s + 128;

    const int tid  = threadIdx.x;
    const int lane = tid & 31;
    const int warp = tid >> 5;
    const int wm   = warp & 3;
    const int wn   = warp >> 2;
    const int g    = lane >> 2;
    const int t    = lane & 3;
    const int bRow = blockIdx.y * 128;
    const int bCol = blockIdx.x * 128;

    if (tid < 128) {
        bias_s[tid] = bias[bCol + tid];
        if (MODE == 3) {
            avs[tid]       = av0[bCol + tid];
            avs[128 + tid] = av1[bCol + tid];
            avs[256 + tid] = av2[bCol + tid];
            avs[384 + tid] = av3[bCol + tid];
        }
    }

    float acc[2][8][4];
#pragma unroll
    for (int mi = 0; mi < 2; mi++)
#pragma unroll
        for (int ni = 0; ni < 8; ni++)
#pragma unroll
            for (int r = 0; r < 4; r++) acc[mi][ni][r] = 0.f;

    auto issue = [&](int k0, int buf) {
        __half* a_dst = Ah + buf * 128 * AHH;
        __half* b_dst = Bh + buf * 128 * AHH;
#pragma unroll
        for (int it = 0; it < 2; it++) {
            int idx = it * 256 + tid;
            int row = idx >> 2, ch = idx & 3;
            const __half* src = A0 + (size_t)(bRow + row) * K + k0 + ch * 8;
            unsigned d = (unsigned)__cvta_generic_to_shared(a_dst + row * AHH + ch * 8);
            int sz = (bRow + row < M) ? 16 : 0;
            asm volatile("cp.async.ca.shared.global [%0], [%1], 16, %2;"
                         :: "r"(d), "l"(src), "r"(sz));
        }
        const int kt = k0 >> 5;
#pragma unroll
        for (int it = 0; it < 2; it++) {
            int idx = it * 256 + tid;
            int n = idx >> 2, ch = idx & 3;
            const __half* src = Bt + ((size_t)kt * N + bCol + n) * 32 + ch * 8;
            unsigned d = (unsigned)__cvta_generic_to_shared(b_dst + n * AHH + ch * 8);
            asm volatile("cp.async.ca.shared.global [%0], [%1], 16;"
                         :: "r"(d), "l"(src));
        }
        asm volatile("cp.async.commit_group;");
    };

    const int S = K / 32;
    issue(0, 0);
    int buf = 0;

    for (int s = 0; s < S; s++) {
        asm volatile("cp.async.wait_group 0;");
        __syncthreads();
        if (s + 1 < S) issue((s + 1) * 32, buf ^ 1);

        const __half* ah = Ah + buf * 128 * AHH;
        const __half* bh = Bh + buf * 128 * AHH;
#pragma unroll
        for (int ks = 0; ks < 2; ks++) {
            uint32_t af[2][4];
#pragma unroll
            for (int mi = 0; mi < 2; mi++) {
                const int mr = wm * 32 + mi * 16;
                af[mi][0] = *(const uint32_t*)&ah[(mr + g)     * AHH + ks * 16 + 2 * t];
                af[mi][1] = *(const uint32_t*)&ah[(mr + g + 8) * AHH + ks * 16 + 2 * t];
                af[mi][2] = *(const uint32_t*)&ah[(mr + g)     * AHH + ks * 16 + 2 * t + 8];
                af[mi][3] = *(const uint32_t*)&ah[(mr + g + 8) * AHH + ks * 16 + 2 * t + 8];
            }
#pragma unroll
            for (int ni = 0; ni < 8; ni++) {
                const int n8 = wn * 8 + ni;
                uint32_t b0 = *(const uint32_t*)&bh[(n8 * 8 + g) * AHH + ks * 16 + 2 * t];
                uint32_t b1 = *(const uint32_t*)&bh[(n8 * 8 + g) * AHH + ks * 16 + 2 * t + 8];
#pragma unroll
                for (int mi = 0; mi < 2; mi++) {
                    asm volatile(
                        "mma.sync.aligned.m16n8k16.row.col.f32.f16.f16.f32 "
                        "{%0,%1,%2,%3}, {%4,%5,%6,%7}, {%8,%9}, {%0,%1,%2,%3};"
                        : "+f"(acc[mi][ni][0]), "+f"(acc[mi][ni][1]),
                          "+f"(acc[mi][ni][2]), "+f"(acc[mi][ni][3])
                        : "r"(af[mi][0]), "r"(af[mi][1]), "r"(af[mi][2]), "r"(af[mi][3]),
                          "r"(b0), "r"(b1));
                }
            }
        }
        buf ^= 1;
    }

#pragma unroll
    for (int mi = 0; mi < 2; mi++) {
        const int r0 = bRow + wm * 32 + mi * 16 + g;
#pragma unroll
        for (int ni = 0; ni < 8; ni++) {
            const int cl = wn * 64 + ni * 8 + t * 2;
            const int c0 = bCol + cl;
            if (r0 < M) {
                __half2 v = __floats2half2_rn(acc[mi][ni][0] + bias_s[cl],
                                              acc[mi][ni][1] + bias_s[cl + 1]);
                *(__half2*)&C[(size_t)r0 * N + c0] = v;
            }
            if (r0 + 8 < M) {
                __half2 v = __floats2half2_rn(acc[mi][ni][2] + bias_s[cl],
                                              acc[mi][ni][3] + bias_s[cl + 1]);
                *(__half2*)&C[(size_t)(r0 + 8) * N + c0] = v;
            }
        }
    }
    if (MODE == 3) {
        float* svs[4] = {s0, s1, s2, s3};
        const int headbase = 4 * blockIdx.x + wn * 2;
#pragma unroll
        for (int v = 0; v < 4; v++) {
#pragma unroll
            for (int mi = 0; mi < 2; mi++) {
                float sA0 = 0.f, sA1 = 0.f, sB0 = 0.f, sB1 = 0.f;
#pragma unroll
                for (int ni = 0; ni < 8; ni++) {
                    const int cl = wn * 64 + ni * 8 + t * 2;
                    float a0v = avs[v * 128 + cl];
                    float a1v = avs[v * 128 + cl + 1];
                    float dA = (acc[mi][ni][0] + bias_s[cl]) * a0v +
                               (acc[mi][ni][1] + bias_s[cl + 1]) * a1v;
                    float dB = (acc[mi][ni][2] + bias_s[cl]) * a0v +
                               (acc[mi][ni][3] + bias_s[cl + 1]) * a1v;
                    if (ni < 4) { sA0 += dA; sB0 += dB; }
                    else        { sA1 += dA; sB1 += dB; }
                }
                sA0 += __shfl_xor_sync(0xffffffffu, sA0, 1);
                sA0 += __shfl_xor_sync(0xffffffffu, sA0, 2);
                sA1 += __shfl_xor_sync(0xffffffffu, sA1, 1);
                sA1 += __shfl_xor_sync(0xffffffffu, sA1, 2);
                sB0 += __shfl_xor_sync(0xffffffffu, sB0, 1);
                sB0 += __shfl_xor_sync(0xffffffffu, sB0, 2);
                sB1 += __shfl_xor_sync(0xffffffffu, sB1, 1);
                sB1 += __shfl_xor_sync(0xffffffffu, sB1, 2);
                if (t == 0) {
                    int nodeA = bRow + wm * 32 + mi * 16 + g;
                    int nodeB = nodeA + 8;
                    if (nodeA < M) {
                        svs[v][nodeA * HH + headbase]     = sA0;
                        svs[v][nodeA * HH + headbase + 1] = sA1;
                    }
                    if (nodeB < M) {
                        svs[v][nodeB * HH + headbase]     = sB0;
                        svs[v][nodeB * HH + headbase + 1] = sB1;
                    }
                }
            }
        }
    }
}

// =============================================================================
// fp16 GEMM h1: merged semantic reduction
// =============================================================================
#define SMEM_H1 ((4 * 128 * AHH) * 2 + (128 + 128 + 256) * 4)

__global__ void __launch_bounds__(256, 2)
gemm_h1(const __half* __restrict__ A0, const __half* __restrict__ Bt,
        const float* __restrict__ bias, const float* __restrict__ qv,
        float* __restrict__ score, float* __restrict__ score2,
        int M, int N, int K, int Mv1)
{
    extern __shared__ char smh[];
    __half* Ah = (__half*)smh;
    __half* Bh = Ah + 2 * 128 * AHH;
    float* bias_s = (float*)(Bh + 2 * 128 * AHH);
    float* q_s    = bias_s + 128;
    float* red    = q_s + 128;

    const int tid  = threadIdx.x;
    const int lane = tid & 31;
    const int warp = tid >> 5;
    const int wm   = warp & 3;
    const int wn   = warp >> 2;
    const int g    = lane >> 2;
    const int t    = lane & 3;
    const int bRow = blockIdx.y * 128;
    const int bCol = blockIdx.x * 128;

    int Mlim = M;
    float* sc = score;
    if (bRow >= MP) sc = score2;
    else Mlim = Mv1;

    if (tid < 128) {
        bias_s[tid] = bias[bCol + tid];
        q_s[tid] = qv[bCol + tid];
    }

    float acc[2][8][4];
#pragma unroll
    for (int mi = 0; mi < 2; mi++)
#pragma unroll
        for (int ni = 0; ni < 8; ni++)
#pragma unroll
            for (int r = 0; r < 4; r++) acc[mi][ni][r] = 0.f;

    auto issue = [&](int k0, int buf) {
        __half* a_dst = Ah + buf * 128 * AHH;
        __half* b_dst = Bh + buf * 128 * AHH;
#pragma unroll
        for (int it = 0; it < 2; it++) {
            int idx = it * 256 + tid;
            int row = idx >> 2, ch = idx & 3;
            const __half* src = A0 + (size_t)(bRow + row) * K + k0 + ch * 8;
            unsigned d = (unsigned)__cvta_generic_to_shared(a_dst + row * AHH + ch * 8);
            int sz = (bRow + row < Mlim) ? 16 : 0;
            asm volatile("cp.async.ca.shared.global [%0], [%1], 16, %2;"
                         :: "r"(d), "l"(src), "r"(sz));
        }
        const int kt = k0 >> 5;
#pragma unroll
        for (int it = 0; it < 2; it++) {
            int idx = it * 256 + tid;
            int n = idx >> 2, ch = idx & 3;
            const __half* src = Bt + ((size_t)kt * N + bCol + n) * 32 + ch * 8;
            unsigned d = (unsigned)__cvta_generic_to_shared(b_dst + n * AHH + ch * 8);
            asm volatile("cp.async.ca.shared.global [%0], [%1], 16;"
                         :: "r"(d), "l"(src));
        }
        asm volatile("cp.async.commit_group;");
    };

    const int S = K / 32;
    issue(0, 0);
    int buf = 0;

    for (int s = 0; s < S; s++) {
        asm volatile("cp.async.wait_group 0;");
        __syncthreads();
        if (s + 1 < S) issue((s + 1) * 32, buf ^ 1);

        const __half* ah = Ah + buf * 128 * AHH;
        const __half* bh = Bh + buf * 128 * AHH;
#pragma unroll
        for (int ks = 0; ks < 2; ks++) {
            uint32_t af[2][4];
#pragma unroll
            for (int mi = 0; mi < 2; mi++) {
                const int mr = wm * 32 + mi * 16;
                af[mi][0] = *(const uint32_t*)&ah[(mr + g)     * AHH + ks * 16 + 2 * t];
                af[mi][1] = *(const uint32_t*)&ah[(mr + g + 8) * AHH + ks * 16 + 2 * t];
                af[mi][2] = *(const uint32_t*)&ah[(mr + g)     * AHH + ks * 16 + 2 * t + 8];
                af[mi][3] = *(const uint32_t*)&ah[(mr + g + 8) * AHH + ks * 16 + 2 * t + 8];
            }
#pragma unroll
            for (int ni = 0; ni < 8; ni++) {
                const int n8 = wn * 8 + ni;
                uint32_t b0 = *(const uint32_t*)&bh[(n8 * 8 + g) * AHH + ks * 16 + 2 * t];
                uint32_t b1 = *(const uint32_t*)&bh[(n8 * 8 + g) * AHH + ks * 16 + 2 * t + 8];
#pragma unroll
                for (int mi = 0; mi < 2; mi++) {
                    asm volatile(
                        "mma.sync.aligned.m16n8k16.row.col.f32.f16.f16.f32 "
                        "{%0,%1,%2,%3}, {%4,%5,%6,%7}, {%8,%9}, {%0,%1,%2,%3};"
                        : "+f"(acc[mi][ni][0]), "+f"(acc[mi][ni][1]),
                          "+f"(acc[mi][ni][2]), "+f"(acc[mi][ni][3])
                        : "r"(af[mi][0]), "r"(af[mi][1]), "r"(af[mi][2]), "r"(af[mi][3]),
                          "r"(b0), "r"(b1));
                }
            }
        }
        buf ^= 1;
    }

    float local = 0.f;
#pragma unroll
    for (int mi = 0; mi < 2; mi++) {
        const int r0 = bRow + wm * 32 + mi * 16 + g;
#pragma unroll
        for (int ni = 0; ni < 8; ni++) {
            const int cl = wn * 64 + ni * 8 + t * 2;
            if (r0 < Mlim)
                local += q_s[cl]     * tanhf(acc[mi][ni][0] + bias_s[cl]) +
                         q_s[cl + 1] * tanhf(acc[mi][ni][1] + bias_s[cl + 1]);
            if (r0 + 8 < Mlim)
                local += q_s[cl]     * tanhf(acc[mi][ni][2] + bias_s[cl]) +
                         q_s[cl + 1] * tanhf(acc[mi][ni][3] + bias_s[cl + 1]);
        }
    }
    red[tid] = local;
    __syncthreads();
    for (int st = 128; st > 0; st >>= 1) {
        if (tid < st) red[tid] += red[tid + st];
        __syncthreads();
    }
    if (tid == 0) atomicAdd(sc, red[0]);
}

// =============================================================================
// fp16 GEMM h2: merged tail, softmax in-kernel
// =============================================================================
#define SMEM_H2 ((6 * 128 * AHH) * 2 + 128 * 4)

__global__ void __launch_bounds__(256, 2)
gemm_h2(const __half* __restrict__ A0, const __half* __restrict__ A1,
        const __half* __restrict__ Bt, const float* __restrict__ bias,
        const float* __restrict__ scores, float* __restrict__ C,
        int M, int N, int K, int Mv1, float invNr, float invNd)
{
    extern __shared__ char smh[];
    __half* A0h = (__half*)smh;
    __half* A1h = A0h + 2 * 128 * AHH;
    __half* Bh  = A1h + 2 * 128 * AHH;
    float* bias_s = (float*)(Bh + 2 * 128 * AHH);

    const int tid  = threadIdx.x;
    const int lane = tid & 31;
    const int warp = tid >> 5;
    const int wm   = warp & 3;
    const int wn   = warp >> 2;
    const int g    = lane >> 2;
    const int t    = lane & 3;
    const int bRow = blockIdx.y * 128;
    const int bCol = blockIdx.x * 128;

    const bool isDis = (bRow >= MP);
    const int Mlim = isDis ? M : Mv1;
    const int rshift = isDis ? (MP - Mv1) : 0;

    if (tid < 128) bias_s[tid] = bias[bCol + tid];

    float invN = isDis ? invNd : invNr;
    float sa = scores[isDis ? 2 : 0] * invN;
    float sb = scores[isDis ? 3 : 1] * invN;
    float mx = fmaxf(sa, sb);
    float e0 = expf(sa - mx), e1 = expf(sb - mx);
    const float w0 = e0 / (e0 + e1);
    const float w1 = e1 / (e0 + e1);

    float acc[2][8][4];
#pragma unroll
    for (int mi = 0; mi < 2; mi++)
#pragma unroll
        for (int ni = 0; ni < 8; ni++)
#pragma unroll
            for (int r = 0; r < 4; r++) acc[mi][ni][r] = 0.f;

    auto issue = [&](int k0, int buf) {
        __half* a0_dst = A0h + buf * 128 * AHH;
        __half* a1_dst = A1h + buf * 128 * AHH;
        __half* b_dst  = Bh + buf * 128 * AHH;
#pragma unroll
        for (int it = 0; it < 2; it++) {
            int idx = it * 256 + tid;
            int row = idx >> 2, ch = idx & 3;
            int sz = (bRow + row < Mlim) ? 16 : 0;
            const __half* s0 = A0 + (size_t)(bRow + row) * K + k0 + ch * 8;
            unsigned d0 = (unsigned)__cvta_generic_to_shared(a0_dst + row * AHH + ch * 8);
            asm volatile("cp.async.ca.shared.global [%0], [%1], 16, %2;"
                         :: "r"(d0), "l"(s0), "r"(sz));
            const __half* s1 = A1 + (size_t)(bRow + row) * K + k0 + ch * 8;
            unsigned d1 = (unsigned)__cvta_generic_to_shared(a1_dst + row * AHH + ch * 8);
            asm volatile("cp.async.ca.shared.global [%0], [%1], 16, %2;"
                         :: "r"(d1), "l"(s1), "r"(sz));
        }
        const int kt = k0 >> 5;
#pragma unroll
        for (int it = 0; it < 2; it++) {
            int idx = it * 256 + tid;
            int n = idx >> 2, ch = idx & 3;
            const __half* src = Bt + ((size_t)kt * N + bCol + n) * 32 + ch * 8;
            unsigned d = (unsigned)__cvta_generic_to_shared(b_dst + n * AHH + ch * 8);
            asm volatile("cp.async.ca.shared.global [%0], [%1], 16;"
                         :: "r"(d), "l"(src));
        }
        asm volatile("cp.async.commit_group;");
    };

    const int S = K / 32;
    issue(0, 0);
    int buf = 0;

    for (int s = 0; s < S; s++) {
        asm volatile("cp.async.wait_group 0;");
        __syncthreads();
        if (s + 1 < S) issue((s + 1) * 32, buf ^ 1);

        const __half* a0p = A0h + buf * 128 * AHH;
        const __half* a1p = A1h + buf * 128 * AHH;
        const __half* bh  = Bh + buf * 128 * AHH;
#pragma unroll
        for (int ks = 0; ks < 2; ks++) {
            uint32_t af[2][4];
#pragma unroll
            for (int mi = 0; mi < 2; mi++) {
                const int mr = wm * 32 + mi * 16;
                const int o[4] = {(mr + g) * AHH + ks * 16 + 2 * t,
                                  (mr + g + 8) * AHH + ks * 16 + 2 * t,
                                  (mr + g) * AHH + ks * 16 + 2 * t + 8,
                                  (mr + g + 8) * AHH + ks * 16 + 2 * t + 8};
#pragma unroll
                for (int r = 0; r < 4; r++) {
                    __half2 x0 = *(const __half2*)&a0p[o[r]];
                    __half2 x1 = *(const __half2*)&a1p[o[r]];
                    float2 f0 = __half22float2(x0);
                    float2 f1 = __half22float2(x1);
                    __half2 hr = __floats2half2_rn(w0 * f0.x + w1 * f1.x,
                                                   w0 * f0.y + w1 * f1.y);
                    af[mi][r] = *(uint32_t*)&hr;
                }
            }
#pragma unroll
            for (int ni = 0; ni < 8; ni++) {
                const int n8 = wn * 8 + ni;
                uint32_t b0 = *(const uint32_t*)&bh[(n8 * 8 + g) * AHH + ks * 16 + 2 * t];
                uint32_t b1 = *(const uint32_t*)&bh[(n8 * 8 + g) * AHH + ks * 16 + 2 * t + 8];
#pragma unroll
                for (int mi = 0; mi < 2; mi++) {
                    asm volatile(
                        "mma.sync.aligned.m16n8k16.row.col.f32.f16.f16.f32 "
                        "{%0,%1,%2,%3}, {%4,%5,%6,%7}, {%8,%9}, {%0,%1,%2,%3};"
                        : "+f"(acc[mi][ni][0]), "+f"(acc[mi][ni][1]),
                          "+f"(acc[mi][ni][2]), "+f"(acc[mi][ni][3])
                        : "r"(af[mi][0]), "r"(af[mi][1]), "r"(af[mi][2]), "r"(af[mi][3]),
                          "r"(b0), "r"(b1));
                }
            }
        }
        buf ^= 1;
    }

#pragma unroll
    for (int mi = 0; mi < 2; mi++) {
        const int r0 = bRow + wm * 32 + mi * 16 + g;
#pragma unroll
        for (int ni = 0; ni < 8; ni++) {
            const int cl = wn * 64 + ni * 8 + t * 2;
            const int c0 = bCol + cl;
            if (r0 < Mlim) {
                float2 v = make_float2(acc[mi][ni][0] + bias_s[cl],
                                       acc[mi][ni][1] + bias_s[cl + 1]);
                *(float2*)&C[(size_t)(r0 - rshift) * N + c0] = v;
            }
            if (r0 + 8 < Mlim) {
                float2 v = make_float2(acc[mi][ni][2] + bias_s[cl],
                                       acc[mi][ni][3] + bias_s[cl + 1]);
                *(float2*)&C[(size_t)(r0 + 8 - rshift) * N + c0] = v;
            }
        }
    }
}

// ================= fused CSR build ==========================================
__global__ void hist4_k(const int* __restrict__ d0, const int* __restrict__ d1,
                        const int* __restrict__ d2, const int* __restrict__ d3,
                        int* __restrict__ cnt)
{
    int i = blockIdx.x * blockDim.x + threadIdx.x;
    if (i < E_RD)                     atomicAdd(&cnt[d0[i]], 1);
    else if (i < E_RD + E_DR)         atomicAdd(&cnt[N_D + d1[i - E_RD]], 1);
    else if (i < E_RD + E_DR + E_RR)  atomicAdd(&cnt[N_D + N_R + d2[i - E_RD - E_DR]], 1);
    else if (i < E_TOT)               atomicAdd(&cnt[N_D + 2 * N_R + d3[i - E_RD - E_DR - E_RR]], 1);
}

__global__ void __launch_bounds__(1024)
scan4_k(const int* __restrict__ cnt, int* __restrict__ rptr_all)
{
    __shared__ int wsum[32];
    __shared__ int s_carry;
    const int b = blockIdx.x;
    const int n    = (b == 0 || b == 3) ? N_D : N_R;
    const int cofs = (b == 0) ? 0 : (b == 1) ? N_D : (b == 2) ? (N_D + N_R) : (N_D + 2 * N_R);
    const int* c = cnt + cofs;
    int* rptr = rptr_all + b * (N_R + 1);

    const int tid = threadIdx.x;
    const int lane = tid & 31, wid = tid >> 5;
    if (tid == 0) s_carry = 0;
    __syncthreads();
    for (int base = 0; base < n; base += 1024) {
        int i = base + tid;
        int v = (i < n) ? c[i] : 0;
        int x = v;
#pragma unroll
        for (int o = 1; o < 32; o <<= 1) {
            int y = __shfl_up_sync(0xffffffffu, x, o);
            if (lane >= o) x += y;
        }
        if (lane == 31) wsum[wid] = x;
        __syncthreads();
        if (wid == 0) {
            int tv = wsum[lane];
#pragma unroll
            for (int o = 1; o < 32; o <<= 1) {
                int y = __shfl_up_sync(0xffffffffu, tv, o);
                if (lane >= o) tv += y;
            }
            wsum[lane] = tv;
        }
        __syncthreads();
        int incl = x + (wid > 0 ? wsum[wid - 1] : 0);
        int carry = s_carry;
        if (i < n) rptr[i] = carry + incl - v;
        __syncthreads();
        if (tid == 1023) s_carry = carry + incl;
        __syncthreads();
    }
    if (tid == 0) rptr[n] = s_carry;
}

__global__ void scatter4_k(const int* __restrict__ s0, const int* __restrict__ d0,
                           const int* __restrict__ s1, const int* __restrict__ d1,
                           const int* __restrict__ s2, const int* __restrict__ d2,
                           const int* __restrict__ s3, const int* __restrict__ d3,
                           const int* __restrict__ rptr_all,
                           int* __restrict__ fill, int* __restrict__ ssort)
{
    int i = blockIdx.x * blockDim.x + threadIdx.x;
    const int* sp; const int* dp; const int* rp; int* fl; int* ss; int e;
    if (i < E_RD) {
        e = i; sp = s0; dp = d0; rp = rptr_all; fl = fill; ss = ssort;
    } else if (i < E_RD + E_DR) {
        e = i - E_RD; sp = s1; dp = d1; rp = rptr_all + (N_R + 1);
        fl = fill + N_D; ss = ssort + E_RD;
    } else if (i < E_RD + E_DR + E_RR) {
        e = i - E_RD - E_DR; sp = s2; dp = d2; rp = rptr_all + 2 * (N_R + 1);
        fl = fill + N_D + N_R; ss = ssort + E_RD + E_DR;
    } else if (i < E_TOT) {
        e = i - E_RD - E_DR - E_RR; sp = s3; dp = d3; rp = rptr_all + 3 * (N_R + 1);
        fl = fill + N_D + 2 * N_R; ss = ssort + E_RD + E_DR + E_RR;
    } else return;
    int d = dp[e];
    int pos = rp[d] + atomicAdd(&fl[d], 1);
    ss[pos] = sp[e];
}

// ============ edge aggregation: single pass, fp16 gather + fp16 output ======
__device__ __forceinline__ float lrelu(float x) { return x > 0.f ? x : 0.2f * x; }

__global__ void __launch_bounds__(256)
agg_csr_k(const int* __restrict__ rptr, const int* __restrict__ ssort,
          const float* __restrict__ ssrc, const float* __restrict__ sdst,
          const __half* __restrict__ x, __half* __restrict__ out, int Nd)
{
    const int warp = (blockIdx.x * blockDim.x + threadIdx.x) >> 5;
    const int lane = threadIdx.x & 31;
    if (warp >= Nd) return;
    const int beg = rptr[warp], end = rptr[warp + 1];

    const int h2 = lane >> 2;
    const float sd2 = sdst[warp * HH + h2];

    float s = 0.f;
    float a0 = 0.f, a1 = 0.f, a2 = 0.f, a3 = 0.f;
    float a4 = 0.f, a5 = 0.f, a6 = 0.f, a7 = 0.f;
    for (int p = beg; p < end; p++) {
        int src = ssort[p];
        float w = expf(lrelu(ssrc[src * HH + h2] + sd2));
        s += w;
        uint4 pk = *(const uint4*)(x + (size_t)src * CC + lane * 8);
        float2 f0 = __half22float2(*(__half2*)&pk.x);
        float2 f1 = __half22float2(*(__half2*)&pk.y);
        float2 f2 = __half22float2(*(__half2*)&pk.z);
        float2 f3 = __half22float2(*(__half2*)&pk.w);
        a0 += w * f0.x; a1 += w * f0.y; a2 += w * f1.x; a3 += w * f1.y;
        a4 += w * f2.x; a5 += w * f2.y; a6 += w * f3.x; a7 += w * f3.y;
    }
    float inv = 1.f / (s + 1e-16f);
    __half2 h0 = __floats2half2_rn(fmaxf(a0 * inv, 0.f), fmaxf(a1 * inv, 0.f));
    __half2 h1 = __floats2half2_rn(fmaxf(a2 * inv, 0.f), fmaxf(a3 * inv, 0.f));
    __half2 hh = __floats2half2_rn(fmaxf(a4 * inv, 0.f), fmaxf(a5 * inv, 0.f));
    __half2 h3 = __floats2half2_rn(fmaxf(a6 * inv, 0.f), fmaxf(a7 * inv, 0.f));
    uint4 pk;
    pk.x = *(uint32_t*)&h0; pk.y = *(uint32_t*)&h1;
    pk.z = *(uint32_t*)&hh; pk.w = *(uint32_t*)&h3;
    *(uint4*)(out + (size_t)warp * CC + lane * 8) = pk;
}

// ---------------------------------------------------------------------------
extern "C" void kernel_launch(void* const* d_in, const int* in_sizes, int n_in,
                              void* d_out, int out_size)
{
    const float* x_rna   = (const float*)d_in[0];
    const float* x_dis   = (const float*)d_in[1];
    const float* W_d     = (const float*)d_in[2];
    const float* b_d     = (const float*)d_in[3];
    const float* Wp_rna  = (const float*)d_in[4];
    const float* bp_rna  = (const float*)d_in[5];
    const float* Wp_dis  = (const float*)d_in[6];
    const float* bp_dis  = (const float*)d_in[7];
    const float* a_src_rd = (const float*)d_in[8];
    const float* a_dst_rd = (const float*)d_in[9];
    const float* a_src_dr = (const float*)d_in[10];
    const float* a_dst_dr = (const float*)d_in[11];
    const float* a_src_rr = (const float*)d_in[12];
    const float* a_dst_rr = (const float*)d_in[13];
    const float* a_src_dd = (const float*)d_in[14];
    const float* a_dst_dd = (const float*)d_in[15];
    const float* kW      = (const float*)d_in[16];
    const float* kb      = (const float*)d_in[17];
    const float* qv      = (const float*)d_in[18];
    const float* W_out   = (const float*)d_in[19];
    const float* b_out   = (const float*)d_in[20];
    const int* rd_src = (const int*)d_in[21];
    const int* rd_dst = (const int*)d_in[22];
    const int* dr_src = (const int*)d_in[23];
    const int* dr_dst = (const int*)d_in[24];
    const int* rr_src = (const int*)d_in[25];
    const int* rr_dst = (const int*)d_in[26];
    const int* dd_src = (const int*)d_in[27];
    const int* dd_dst = (const int*)d_in[28];

    float* out = (float*)d_out;

    float *p_sr, *p_sd, *p_scores;
    __half *p_xr, *p_xdis, *p_xd, *p_hr, *p_hd, *p_bufA, *p_bufB;
    __half *p_wdh, *p_wprh, *p_wpdh, *p_kwh, *p_woh;
    int *p_cnt, *p_fill, *p_rptr, *p_ssort;
    cudaGetSymbolAddress((void**)&p_xr, g_xr_h);
    cudaGetSymbolAddress((void**)&p_xdis, g_xdis_h);
    cudaGetSymbolAddress((void**)&p_xd, g_xd);
    cudaGetSymbolAddress((void**)&p_hr, g_hr);
    cudaGetSymbolAddress((void**)&p_hd, g_hd);
    cudaGetSymbolAddress((void**)&p_bufA, g_bufA);
    cudaGetSymbolAddress((void**)&p_bufB, g_bufB);
    cudaGetSymbolAddress((void**)&p_sr, g_s_rna);
    cudaGetSymbolAddress((void**)&p_sd, g_s_dis);
    cudaGetSymbolAddress((void**)&p_cnt, g_cnt);
    cudaGetSymbolAddress((void**)&p_fill, g_fill);
    cudaGetSymbolAddress((void**)&p_rptr, g_rptr);
    cudaGetSymbolAddress((void**)&p_ssort, g_ssort);
    cudaGetSymbolAddress((void**)&p_scores, g_scores);
    cudaGetSymbolAddress((void**)&p_wdh, g_wd_h);
    cudaGetSymbolAddress((void**)&p_wprh, g_wpr_h);
    cudaGetSymbolAddress((void**)&p_wpdh, g_wpd_h);
    cudaGetSymbolAddress((void**)&p_kwh, g_kw_h);
    cudaGetSymbolAddress((void**)&p_woh, g_wo_h);

    cudaFuncSetAttribute(gemm_hp<0>, cudaFuncAttributeMaxDynamicSharedMemorySize, SMEM_HP);
    cudaFuncSetAttribute(gemm_hp<3>, cudaFuncAttributeMaxDynamicSharedMemorySize, SMEM_HP);
    cudaFuncSetAttribute(gemm_h1, cudaFuncAttributeMaxDynamicSharedMemorySize, SMEM_H1);
    cudaFuncSetAttribute(gemm_h2, cudaFuncAttributeMaxDynamicSharedMemorySize, SMEM_H2);

    const dim3 thr(256);
    const int mbr = (N_R + 127) / 128;   // 391
    const int mbd = (N_D + 127) / 128;   // 79
    const int mbt = (MT + 127) / 128;    // 470

    __half* p_odr = p_bufA;
    __half* p_ord = p_bufA + (size_t)MP * CC;
    __half* p_orr = p_bufB;
    __half* p_odd = p_bufB + (size_t)MP * CC;

    int* rp_rd = p_rptr + 0 * (N_R + 1);
    int* rp_dr = p_rptr + 1 * (N_R + 1);
    int* rp_rr = p_rptr + 2 * (N_R + 1);
    int* rp_dd = p_rptr + 3 * (N_R + 1);
    int* ss_rd = p_ssort;
    int* ss_dr = ss_rd + E_RD;
    int* ss_rr = ss_dr + E_DR;
    int* ss_dd = ss_rr + E_RR;

    cudaStream_t st0 = 0, st1, st2;
    cudaStreamCreateWithFlags(&st1, cudaStreamNonBlocking);
    cudaStreamCreateWithFlags(&st2, cudaStreamNonBlocking);
    cudaEvent_t ev[10];
    for (int i = 0; i < 10; i++) cudaEventCreateWithFlags(&ev[i], cudaEventDisableTiming);

    // fork
    cudaEventRecord(ev[0], st0);
    cudaStreamWaitEvent(st1, ev[0], 0);
    cudaStreamWaitEvent(st2, ev[0], 0);

    // st1: convert x_rna to fp16 (independent; overlaps prep/CSR)
    cvt_h_k<<<(N_R * RNA_IN / 8 + 255) / 256, thr, 0, st1>>>(x_rna, p_xr, N_R * RNA_IN);

    // st2: convert x_dis to fp16, then CSR build
    cvt_h_k<<<(N_D * D_FEAT / 8 + 255) / 256, thr, 0, st2>>>(x_dis, p_xdis, N_D * D_FEAT);
    cudaEventRecord(ev[8], st2);     // x_dis fp16 ready
    cudaMemsetAsync(p_cnt, 0, CNT_TOT * sizeof(int), st2);
    cudaMemsetAsync(p_fill, 0, CNT_TOT * sizeof(int), st2);
    cudaMemsetAsync(p_scores, 0, 4 * sizeof(float), st2);
    hist4_k<<<(E_TOT + 255) / 256, thr, 0, st2>>>(rd_dst, dr_dst, rr_dst, dd_dst, p_cnt);
    scan4_k<<<4, 1024, 0, st2>>>(p_cnt, p_rptr);
    scatter4_k<<<(E_TOT + 255) / 256, thr, 0, st2>>>(rd_src, rd_dst, dr_src, dr_dst,
                                                     rr_src, rr_dst, dd_src, dd_dst,
                                                     p_rptr, p_fill, p_ssort);
    cudaEventRecord(ev[2], st2);     // CSR done

    // st0: weight prep (all fp16), record for st1's hr GEMM
    prep_w_k<<<96, thr, 0, st0>>>(W_d, Wp_rna, Wp_dis, kW, W_out,
                                  p_wdh, p_wprh, p_wpdh, p_kwh, p_woh);
    cudaEventRecord(ev[1], st0);

    // st0: disease chain (needs x_dis fp16)
    cudaStreamWaitEvent(st0, ev[8], 0);
    gemm_hp<0><<<dim3(2, mbd), thr, SMEM_HP, st0>>>(p_xdis, p_wdh, b_d, p_xd,
                                                    nullptr, nullptr, nullptr, nullptr,
                                                    nullptr, nullptr, nullptr, nullptr,
                                                    N_D, RNA_IN, D_FEAT);
    gemm_hp<3><<<dim3(2, mbd), thr, SMEM_HP, st0>>>(p_xd, p_wpdh, bp_dis, p_hd,
                                                    a_dst_rd, a_src_dr, a_src_dd, a_dst_dd,
                                                    p_sd + 0 * N_D * HH, p_sd + 1 * N_D * HH,
                                                    p_sd + 2 * N_D * HH, p_sd + 3 * N_D * HH,
                                                    N_D, CC, RNA_IN);
    cudaEventRecord(ev[3], st0);     // hd + dis scores ready

    // st1: rna chain (cvt_xr in-order; needs prep)
    cudaStreamWaitEvent(st1, ev[1], 0);
    gemm_hp<3><<<dim3(2, mbr), thr, SMEM_HP, st1>>>(p_xr, p_wprh, bp_rna, p_hr,
                                                    a_src_rd, a_dst_dr, a_src_rr, a_dst_rr,
                                                    p_sr + 0 * N_R * HH, p_sr + 1 * N_R * HH,
                                                    p_sr + 2 * N_R * HH, p_sr + 3 * N_R * HH,
                                                    N_R, CC, RNA_IN);
    cudaEventRecord(ev[4], st1);     // hr + rna scores ready

    // st1: agg_rr
    cudaStreamWaitEvent(st1, ev[2], 0);
    agg_csr_k<<<(N_R * 32 + 255) / 256, thr, 0, st1>>>(rp_rr, ss_rr,
                                                       p_sr + 2 * N_R * HH, p_sr + 3 * N_R * HH,
                                                       p_hr, p_orr, N_R);

    // st0: agg_dr
    cudaStreamWaitEvent(st0, ev[4], 0);
    cudaStreamWaitEvent(st0, ev[2], 0);
    agg_csr_k<<<(N_R * 32 + 255) / 256, thr, 0, st0>>>(rp_dr, ss_dr,
                                                       p_sd + 1 * N_D * HH, p_sr + 1 * N_R * HH,
                                                       p_hd, p_odr, N_R);

    // st2: agg_dd then agg_rd
    cudaStreamWaitEvent(st2, ev[3], 0);
    agg_csr_k<<<(N_D * 32 + 255) / 256, thr, 0, st2>>>(rp_dd, ss_dd,
                                                       p_sd + 2 * N_D * HH, p_sd + 3 * N_D * HH,
                                                       p_hd, p_odd, N_D);
    cudaEventRecord(ev[5], st2);
    cudaStreamWaitEvent(st2, ev[4], 0);
    agg_csr_k<<<(N_D * 32 + 255) / 256, thr, 0, st2>>>(rp_rd, ss_rd,
                                                       p_sr + 0 * N_R * HH, p_sd + 0 * N_D * HH,
                                                       p_hr, p_ord, N_D);
    cudaEventRecord(ev[6], st2);

    // st0: semantic(bufA)
    cudaStreamWaitEvent(st0, ev[6], 0);
    gemm_h1<<<dim3(2, mbt), thr, SMEM_H1, st0>>>(p_bufA, p_kwh, kb, qv,
                                                 p_scores + 0, p_scores + 2,
                                                 MT, CC, CC, N_R);

    // st1: semantic(bufB)
    cudaStreamWaitEvent(st1, ev[5], 0);
    gemm_h1<<<dim3(2, mbt), thr, SMEM_H1, st1>>>(p_bufB, p_kwh, kb, qv,
                                                 p_scores + 1, p_scores + 3,
                                                 MT, CC, CC, N_R);
    cudaEventRecord(ev[7], st1);

    // st0: merged tail GEMM with in-kernel softmax
    cudaStreamWaitEvent(st0, ev[7], 0);
    gemm_h2<<<dim3(2, mbt), thr, SMEM_H2, st0>>>(p_bufA, p_bufB, p_woh, b_out,
                                                 p_scores, out, MT, CC, CC, N_R,
                                                 1.f / N_R, 1.f / N_D);

    for (int i = 0; i < 10; i++) cudaEventDestroy(ev[i]);
    cudaStreamDestroy(st1);
    cudaStreamDestroy(st2);
}